// round 1
// baseline (speedup 1.0000x reference)
#include <cuda_runtime.h>
#include <cstdint>

#define BATCH    16384
#define NFIELDS  50
#define DIM      64
#define L1DIM    128
#define L2DIM    64
#define ROWS     32      // batch rows per block
#define THREADS  256     // 8 warps

// dynamic shared layout (floats):
//   sW    : 8192   (W1 64x128, later overwritten by W2 128x64)
//   sFM   : ROWS*64
//   sH1   : ROWS*128
//   sH2   : ROWS*64
//   sB1   : 128
//   sB2   : 64
//   sWp   : 64
//   sBias : ROWS
#define SMEM_FLOATS (8192 + ROWS*64 + ROWS*128 + ROWS*64 + 128 + 64 + 64 + ROWS)

__global__ __launch_bounds__(THREADS)
void nfm_fused_kernel(const int*   __restrict__ features,
                      const float* __restrict__ emb,
                      const float* __restrict__ bias_table,
                      const float* __restrict__ w_bias,
                      const float* __restrict__ W1,
                      const float* __restrict__ b1,
                      const float* __restrict__ W2,
                      const float* __restrict__ b2,
                      const float* __restrict__ Wp,
                      const float* __restrict__ bp,
                      float*       __restrict__ out)
{
    extern __shared__ float sm[];
    float* sW    = sm;                    // 8192
    float* sFM   = sW   + 8192;           // ROWS*64
    float* sH1   = sFM  + ROWS*64;        // ROWS*128
    float* sH2   = sH1  + ROWS*128;       // ROWS*64
    float* sB1   = sH2  + ROWS*64;        // 128
    float* sB2   = sB1  + 128;            // 64
    float* sWp   = sB2  + 64;             // 64
    float* sBias = sWp  + 64;             // ROWS

    const int tid  = threadIdx.x;
    const int lane = tid & 31;
    const int wid  = tid >> 5;

    // ---- stage W1 + small params into shared -------------------------------
    {
        const float4* src = reinterpret_cast<const float4*>(W1);
        float4*       dst = reinterpret_cast<float4*>(sW);
        #pragma unroll
        for (int i = tid; i < 2048; i += THREADS) dst[i] = src[i];
        if (tid < 128)                 sB1[tid]       = b1[tid];
        else if (tid < 192)            sB2[tid - 128] = b2[tid - 128];
        else                           sWp[tid - 192] = Wp[tid - 192];
    }

    // ---- gather + FM bi-interaction ----------------------------------------
    // warp w handles local rows w*4 .. w*4+3; full warp per row, float2/lane
    const int row0 = blockIdx.x * ROWS;
    #pragma unroll
    for (int i = 0; i < 4; ++i) {
        const int rl = wid * 4 + i;
        const int rg = row0 + rl;
        const int* fr = features + (long)rg * NFIELDS;
        // preload this row's indices into registers (lane f and f+32)
        const int i0 = fr[lane];                                  // lane 0..31 < 50
        const int i1 = (lane + 32 < NFIELDS) ? fr[lane + 32] : 0;

        float2 s  = make_float2(0.f, 0.f);
        float2 sq = make_float2(0.f, 0.f);
        #pragma unroll
        for (int f = 0; f < NFIELDS; ++f) {
            const int idx = __shfl_sync(0xffffffffu, (f < 32) ? i0 : i1, f & 31);
            const float2 v = *reinterpret_cast<const float2*>(
                                 emb + (long)idx * DIM + lane * 2);
            s.x  += v.x;        s.y  += v.y;
            sq.x += v.x * v.x;  sq.y += v.y * v.y;
        }
        float2 fm;
        fm.x = 0.5f * (s.x * s.x - sq.x);
        fm.y = 0.5f * (s.y * s.y - sq.y);
        *reinterpret_cast<float2*>(sFM + rl * DIM + lane * 2) = fm;

        // first-order feature bias
        float bsum = bias_table[i0] + ((lane + 32 < NFIELDS) ? bias_table[i1] : 0.f);
        #pragma unroll
        for (int o = 16; o; o >>= 1) bsum += __shfl_down_sync(0xffffffffu, bsum, o);
        if (lane == 0) sBias[rl] = bsum;
    }
    __syncthreads();

    // ---- h1 = relu(FM @ W1 + b1)  [ROWS x 128], 4x4 register tile ----------
    {
        const int ct = tid & 31;   // column tile base (cols ct, ct+32, ct+64, ct+96)
        const int rt = tid >> 5;   // row tile (4 rows each)
        float acc[4][4];
        #pragma unroll
        for (int i = 0; i < 4; ++i)
            #pragma unroll
            for (int k = 0; k < 4; ++k) acc[i][k] = sB1[ct + 32 * k];

        #pragma unroll
        for (int d = 0; d < DIM; ++d) {
            const float w0 = sW[d * L1DIM + ct];
            const float w1 = sW[d * L1DIM + ct + 32];
            const float w2 = sW[d * L1DIM + ct + 64];
            const float w3 = sW[d * L1DIM + ct + 96];
            #pragma unroll
            for (int i = 0; i < 4; ++i) {
                const float fv = sFM[(rt * 4 + i) * DIM + d];   // broadcast
                acc[i][0] += fv * w0;  acc[i][1] += fv * w1;
                acc[i][2] += fv * w2;  acc[i][3] += fv * w3;
            }
        }
        #pragma unroll
        for (int i = 0; i < 4; ++i)
            #pragma unroll
            for (int k = 0; k < 4; ++k)
                sH1[(rt * 4 + i) * L1DIM + ct + 32 * k] = fmaxf(acc[i][k], 0.f);
    }
    __syncthreads();

    // ---- overlay W2 into sW -------------------------------------------------
    {
        const float4* src = reinterpret_cast<const float4*>(W2);
        float4*       dst = reinterpret_cast<float4*>(sW);
        #pragma unroll
        for (int i = tid; i < 2048; i += THREADS) dst[i] = src[i];
    }
    __syncthreads();

    // ---- h2 = relu(H1 @ W2 + b2)  [ROWS x 64], 4x2 register tile -----------
    {
        const int ct = tid & 31;   // cols ct, ct+32
        const int rt = tid >> 5;
        float acc[4][2];
        #pragma unroll
        for (int i = 0; i < 4; ++i) {
            acc[i][0] = sB2[ct];
            acc[i][1] = sB2[ct + 32];
        }
        #pragma unroll
        for (int d = 0; d < L1DIM; ++d) {
            const float w0 = sW[d * L2DIM + ct];
            const float w1 = sW[d * L2DIM + ct + 32];
            #pragma unroll
            for (int i = 0; i < 4; ++i) {
                const float h = sH1[(rt * 4 + i) * L1DIM + d];  // broadcast
                acc[i][0] += h * w0;
                acc[i][1] += h * w1;
            }
        }
        #pragma unroll
        for (int i = 0; i < 4; ++i) {
            sH2[(rt * 4 + i) * L2DIM + ct]      = fmaxf(acc[i][0], 0.f);
            sH2[(rt * 4 + i) * L2DIM + ct + 32] = fmaxf(acc[i][1], 0.f);
        }
    }
    __syncthreads();

    // ---- pred = H2 @ Wp + bp, final sum ------------------------------------
    {
        const float gb  = w_bias[0];
        const float bpv = bp[0];
        #pragma unroll
        for (int i = 0; i < 4; ++i) {
            const int rl = wid * 4 + i;
            float v = sH2[rl * L2DIM + lane]      * sWp[lane]
                    + sH2[rl * L2DIM + lane + 32] * sWp[lane + 32];
            #pragma unroll
            for (int o = 16; o; o >>= 1) v += __shfl_down_sync(0xffffffffu, v, o);
            if (lane == 0) out[row0 + rl] = v + bpv + sBias[rl] + gb;
        }
    }
}

extern "C" void kernel_launch(void* const* d_in, const int* in_sizes, int n_in,
                              void* d_out, int out_size)
{
    const int*   features   = (const int*)  d_in[0];
    // d_in[1] = labels (unused, shape-only in reference)
    const float* emb        = (const float*)d_in[2];
    const float* bias_table = (const float*)d_in[3];
    const float* w_bias     = (const float*)d_in[4];
    const float* W1         = (const float*)d_in[5];
    const float* b1         = (const float*)d_in[6];
    const float* W2         = (const float*)d_in[7];
    const float* b2         = (const float*)d_in[8];
    const float* Wp         = (const float*)d_in[9];
    const float* bp         = (const float*)d_in[10];
    float*       out        = (float*)d_out;

    const int smem_bytes = SMEM_FLOATS * sizeof(float);   // ~66.7 KB
    cudaFuncSetAttribute(nfm_fused_kernel,
                         cudaFuncAttributeMaxDynamicSharedMemorySize, smem_bytes);

    nfm_fused_kernel<<<BATCH / ROWS, THREADS, smem_bytes>>>(
        features, emb, bias_table, w_bias, W1, b1, W2, b2, Wp, bp, out);
}

// round 2
// speedup vs baseline: 1.3336x; 1.3336x over previous
#include <cuda_runtime.h>
#include <cstdint>

#define BATCH    16384
#define NFIELDS  50
#define DIM      64
#define L1DIM    128
#define L2DIM    64
#define ROWS     32      // batch rows per block
#define THREADS  256     // 8 warps

// dynamic shared layout (floats):
//   sFM   : ROWS*64   (reused as sH2 after h1 is computed)
//   sH1   : ROWS*128
//   sB1   : 128
//   sB2   : 64
//   sWp   : 64
//   sBias : ROWS
#define SMEM_FLOATS (ROWS*64 + ROWS*128 + 128 + 64 + 64 + ROWS)

__global__ __launch_bounds__(THREADS, 4)
void nfm_fused_kernel(const int*   __restrict__ features,
                      const float* __restrict__ emb,
                      const float* __restrict__ bias_table,
                      const float* __restrict__ w_bias,
                      const float* __restrict__ W1,
                      const float* __restrict__ b1,
                      const float* __restrict__ W2,
                      const float* __restrict__ b2,
                      const float* __restrict__ Wp,
                      const float* __restrict__ bp,
                      float*       __restrict__ out)
{
    extern __shared__ float sm[];
    float* sFM   = sm;                    // ROWS*64, reused as sH2
    float* sH1   = sFM  + ROWS*64;        // ROWS*128
    float* sB1   = sH1  + ROWS*128;       // 128
    float* sB2   = sB1  + 128;            // 64
    float* sWp   = sB2  + 64;             // 64
    float* sBias = sWp  + 64;             // ROWS
    float* sH2   = sFM;                   // overlay

    const int tid  = threadIdx.x;
    const int lane = tid & 31;
    const int wid  = tid >> 5;

    // ---- stage small params into shared ------------------------------------
    if (tid < 128)       sB1[tid]       = b1[tid];
    else if (tid < 192)  sB2[tid - 128] = b2[tid - 128];
    else                 sWp[tid - 192] = Wp[tid - 192];

    // ---- gather + FM bi-interaction ----------------------------------------
    // warp w handles local rows w*4 .. w*4+3; full warp per row, float2/lane
    const int row0 = blockIdx.x * ROWS;
    #pragma unroll
    for (int i = 0; i < 4; ++i) {
        const int rl = wid * 4 + i;
        const int rg = row0 + rl;
        const int* fr = features + (long)rg * NFIELDS;
        // preload this row's indices into registers (lane f and f+32)
        const int i0 = fr[lane];                                  // lane 0..31 < 50
        const int i1 = (lane + 32 < NFIELDS) ? fr[lane + 32] : 0;

        float2 s  = make_float2(0.f, 0.f);
        float2 sq = make_float2(0.f, 0.f);
        #pragma unroll
        for (int f = 0; f < NFIELDS; ++f) {
            const int idx = __shfl_sync(0xffffffffu, (f < 32) ? i0 : i1, f & 31);
            const float2 v = *reinterpret_cast<const float2*>(
                                 emb + (long)idx * DIM + lane * 2);
            s.x  += v.x;        s.y  += v.y;
            sq.x += v.x * v.x;  sq.y += v.y * v.y;
        }
        float2 fm;
        fm.x = 0.5f * (s.x * s.x - sq.x);
        fm.y = 0.5f * (s.y * s.y - sq.y);
        *reinterpret_cast<float2*>(sFM + rl * DIM + lane * 2) = fm;

        // first-order feature bias
        float bsum = bias_table[i0] + ((lane + 32 < NFIELDS) ? bias_table[i1] : 0.f);
        #pragma unroll
        for (int o = 16; o; o >>= 1) bsum += __shfl_down_sync(0xffffffffu, bsum, o);
        if (lane == 0) sBias[rl] = bsum;
    }
    __syncthreads();

    // ---- h1 = relu(FM @ W1 + b1)  [ROWS x 128], 4x4 register tile ----------
    // W1 read from global (L2-resident: all 512 blocks reuse the same 32 KB)
    {
        const int ct = tid & 31;   // column tile base (cols ct, ct+32, ct+64, ct+96)
        const int rt = tid >> 5;   // row tile (4 rows each)
        float acc[4][4];
        #pragma unroll
        for (int i = 0; i < 4; ++i)
            #pragma unroll
            for (int k = 0; k < 4; ++k) acc[i][k] = sB1[ct + 32 * k];

        #pragma unroll
        for (int d = 0; d < DIM; ++d) {
            const float w0 = __ldg(W1 + d * L1DIM + ct);
            const float w1 = __ldg(W1 + d * L1DIM + ct + 32);
            const float w2 = __ldg(W1 + d * L1DIM + ct + 64);
            const float w3 = __ldg(W1 + d * L1DIM + ct + 96);
            #pragma unroll
            for (int i = 0; i < 4; ++i) {
                const float fv = sFM[(rt * 4 + i) * DIM + d];   // broadcast
                acc[i][0] += fv * w0;  acc[i][1] += fv * w1;
                acc[i][2] += fv * w2;  acc[i][3] += fv * w3;
            }
        }
        #pragma unroll
        for (int i = 0; i < 4; ++i)
            #pragma unroll
            for (int k = 0; k < 4; ++k)
                sH1[(rt * 4 + i) * L1DIM + ct + 32 * k] = fmaxf(acc[i][k], 0.f);
    }
    __syncthreads();   // sFM dead from here; safe to overlay sH2

    // ---- h2 = relu(H1 @ W2 + b2)  [ROWS x 64], 4x2 register tile -----------
    {
        const int ct = tid & 31;   // cols ct, ct+32
        const int rt = tid >> 5;
        float acc[4][2];
        #pragma unroll
        for (int i = 0; i < 4; ++i) {
            acc[i][0] = sB2[ct];
            acc[i][1] = sB2[ct + 32];
        }
        #pragma unroll
        for (int d = 0; d < L1DIM; ++d) {
            const float w0 = __ldg(W2 + d * L2DIM + ct);
            const float w1 = __ldg(W2 + d * L2DIM + ct + 32);
            #pragma unroll
            for (int i = 0; i < 4; ++i) {
                const float h = sH1[(rt * 4 + i) * L1DIM + d];  // broadcast
                acc[i][0] += h * w0;
                acc[i][1] += h * w1;
            }
        }
        #pragma unroll
        for (int i = 0; i < 4; ++i) {
            sH2[(rt * 4 + i) * L2DIM + ct]      = fmaxf(acc[i][0], 0.f);
            sH2[(rt * 4 + i) * L2DIM + ct + 32] = fmaxf(acc[i][1], 0.f);
        }
    }
    __syncthreads();

    // ---- pred = H2 @ Wp + bp, final sum ------------------------------------
    {
        const float gb  = __ldg(w_bias);
        const float bpv = __ldg(bp);
        #pragma unroll
        for (int i = 0; i < 4; ++i) {
            const int rl = wid * 4 + i;
            float v = sH2[rl * L2DIM + lane]      * sWp[lane]
                    + sH2[rl * L2DIM + lane + 32] * sWp[lane + 32];
            #pragma unroll
            for (int o = 16; o; o >>= 1) v += __shfl_down_sync(0xffffffffu, v, o);
            if (lane == 0) out[row0 + rl] = v + bpv + sBias[rl] + gb;
        }
    }
}

extern "C" void kernel_launch(void* const* d_in, const int* in_sizes, int n_in,
                              void* d_out, int out_size)
{
    const int*   features   = (const int*)  d_in[0];
    // d_in[1] = labels (unused, shape-only in reference)
    const float* emb        = (const float*)d_in[2];
    const float* bias_table = (const float*)d_in[3];
    const float* w_bias     = (const float*)d_in[4];
    const float* W1         = (const float*)d_in[5];
    const float* b1         = (const float*)d_in[6];
    const float* W2         = (const float*)d_in[7];
    const float* b2         = (const float*)d_in[8];
    const float* Wp         = (const float*)d_in[9];
    const float* bp         = (const float*)d_in[10];
    float*       out        = (float*)d_out;

    const int smem_bytes = SMEM_FLOATS * sizeof(float);   // ~24.6 KB
    cudaFuncSetAttribute(nfm_fused_kernel,
                         cudaFuncAttributeMaxDynamicSharedMemorySize, smem_bytes);

    nfm_fused_kernel<<<BATCH / ROWS, THREADS, smem_bytes>>>(
        features, emb, bias_table, w_bias, W1, b1, W2, b2, Wp, bp, out);
}